// round 3
// baseline (speedup 1.0000x reference)
#include <cuda_runtime.h>
#include <math.h>

// Problem constants
#define BB 4
#define TT 2048
#define DD 512
#define HH 8
#define DH 64
#define LL 2
#define GG 64      // reduce-kernel blocks per batch
#define CHK 64     // gate-kernel blocks per batch
#define EPSF 1e-5f

// Scratch (no device allocation allowed -> __device__ globals)
__device__ float g_part[BB][GG][DD];   // per-block partial sums of rstd*(x-mean)
__device__ float g_M[BB][HH][DD];      // folded per-head D-vectors
__device__ float g_S[BB][HH];          // sum_d M'
__device__ float g_bias[BB][HH];       // sum_d ln_b * M
__device__ float g_valid[2][BB];       // clipped valid counts: [0]=vid mask, [1]=aud mask
__device__ int   g_all[2][BB];         // all-masked flags

// ---------------------------------------------------------------------------
// Kernel 0: mask statistics (valid counts + all-masked flags)
// masks arrive as int32 (harness promotes numpy bool -> int32)
// ---------------------------------------------------------------------------
__global__ void k_counts(const int* __restrict__ vid_kpm,
                         const int* __restrict__ aud_kpm) {
    int m = blockIdx.x >> 2;          // 0 = vid mask, 1 = aud mask
    int b = blockIdx.x & 3;
    const int* kp = (m == 0 ? vid_kpm : aud_kpm) + (size_t)b * TT;
    int cnt = 0;
    for (int t = threadIdx.x; t < TT; t += 256) cnt += (kp[t] == 0);
    __shared__ int sh[256];
    sh[threadIdx.x] = cnt;
    __syncthreads();
    for (int s = 128; s > 0; s >>= 1) {
        if (threadIdx.x < s) sh[threadIdx.x] += sh[threadIdx.x + s];
        __syncthreads();
    }
    if (threadIdx.x == 0) {
        int c = sh[0];
        g_valid[m][b] = fmaxf((float)c, 1.0f);
        g_all[m][b] = (c == 0) ? 1 : 0;
    }
}

// ---------------------------------------------------------------------------
// Kernel A: masked sum over tokens of rstd*(x - mean)  (LN affine deferred)
// grid (GG, BB), 256 threads (8 warps, warp-per-token)
// ---------------------------------------------------------------------------
__global__ void k_reduce(const float* __restrict__ src,
                         const int* __restrict__ kpm) {
    int b = blockIdx.y;
    int blk = blockIdx.x;
    int tid = threadIdx.x;
    int warp = tid >> 5, lane = tid & 31;

    __shared__ float csh[DD];
    csh[tid] = 0.f;
    csh[tid + 256] = 0.f;
    __syncthreads();

    const int TPB = TT / GG;   // 32 tokens per block
    const int TPW = TPB / 8;   // 4 tokens per warp
    int t0 = blk * TPB + warp * TPW;

    float acc[16];
#pragma unroll
    for (int i = 0; i < 16; i++) acc[i] = 0.f;

    for (int i = 0; i < TPW; i++) {
        int t = t0 + i;
        if (kpm[(size_t)b * TT + t]) continue;   // masked token: contributes nothing
        const float4* row = (const float4*)(src + ((size_t)(b * TT + t)) * DD);
        float4 v[4];
        float s = 0.f, sq = 0.f;
#pragma unroll
        for (int k = 0; k < 4; k++) {
            v[k] = row[k * 32 + lane];
            s  += v[k].x + v[k].y + v[k].z + v[k].w;
            sq += v[k].x * v[k].x + v[k].y * v[k].y + v[k].z * v[k].z + v[k].w * v[k].w;
        }
#pragma unroll
        for (int off = 16; off; off >>= 1) {
            s  += __shfl_xor_sync(0xffffffffu, s, off);
            sq += __shfl_xor_sync(0xffffffffu, sq, off);
        }
        float mean = s * (1.f / DD);
        float var  = sq * (1.f / DD) - mean * mean;
        float rstd = rsqrtf(var + EPSF);
        float sub  = rstd * mean;
#pragma unroll
        for (int k = 0; k < 4; k++) {
            acc[k * 4 + 0] += rstd * v[k].x - sub;
            acc[k * 4 + 1] += rstd * v[k].y - sub;
            acc[k * 4 + 2] += rstd * v[k].z - sub;
            acc[k * 4 + 3] += rstd * v[k].w - sub;
        }
    }
    // combine 8 warps into one block partial via shared atomics
#pragma unroll
    for (int k = 0; k < 4; k++) {
        int d = k * 128 + lane * 4;
        atomicAdd(&csh[d + 0], acc[k * 4 + 0]);
        atomicAdd(&csh[d + 1], acc[k * 4 + 1]);
        atomicAdd(&csh[d + 2], acc[k * 4 + 2]);
        atomicAdd(&csh[d + 3], acc[k * 4 + 3]);
    }
    __syncthreads();
    g_part[b][blk][tid]       = csh[tid];
    g_part[b][blk][tid + 256] = csh[tid + 256];
}

// ---------------------------------------------------------------------------
// Kernel B: per (b,h) fold: c = g*acc + cnt*b ; ksum = Wk_head @ c ;
//           M' = (scale/valid) * g ⊙ (Wq_head^T @ ksum) ; plus S, bias
// grid BB*HH blocks, 512 threads
// ---------------------------------------------------------------------------
__global__ void k_mid(const float* __restrict__ Wq, const float* __restrict__ Wk,
                      const float* __restrict__ lng, const float* __restrict__ lnb,
                      int srcm) {
    int b = blockIdx.x >> 3, h = blockIdx.x & 7;
    int tid = threadIdx.x;
    int warp = tid >> 5, lane = tid & 31;

    __shared__ float csh[DD];
    __shared__ float ksh[DH];
    __shared__ float rs[16], rb[16];

    float validf = g_valid[srcm][b];
    float cntf = g_all[srcm][b] ? 0.f : validf;

    float acc = 0.f;
#pragma unroll
    for (int g = 0; g < GG; g++) acc += g_part[b][g][tid];
    csh[tid] = lng[tid] * acc + cntf * lnb[tid];
    __syncthreads();

    // ksum for this head's 64 rows: 16 warps x 4 rows each
#pragma unroll
    for (int jj = 0; jj < 4; jj++) {
        int j = warp * 4 + jj;
        const float* wk = Wk + (size_t)(h * DH + j) * DD;
        float s = 0.f;
#pragma unroll
        for (int k = 0; k < 16; k++) { int d = lane + 32 * k; s += csh[d] * wk[d]; }
#pragma unroll
        for (int off = 16; off; off >>= 1) s += __shfl_xor_sync(0xffffffffu, s, off);
        if (lane == 0) ksh[j] = s;
    }
    __syncthreads();

    float m = 0.f;
#pragma unroll
    for (int j = 0; j < DH; j++) m += ksh[j] * Wq[(size_t)(h * DH + j) * DD + tid];
    m *= 0.125f / validf;                 // scale = dh^-0.5 = 0.125, /valid folded in
    float mp = m * lng[tid];              // fold LN gamma
    g_M[b][h][tid] = mp;

    float sv = mp, bv = lnb[tid] * m;     // S and bias (beta fold)
#pragma unroll
    for (int off = 16; off; off >>= 1) {
        sv += __shfl_xor_sync(0xffffffffu, sv, off);
        bv += __shfl_xor_sync(0xffffffffu, bv, off);
    }
    if (lane == 0) { rs[warp] = sv; rb[warp] = bv; }
    __syncthreads();
    if (tid == 0) {
        float S = 0.f, Bv = 0.f;
        for (int w = 0; w < 16; w++) { S += rs[w]; Bv += rb[w]; }
        g_S[b][h] = S;
        g_bias[b][h] = Bv;
    }
}

// ---------------------------------------------------------------------------
// Kernel C: per token: LN-stats + 8 dots vs M' -> rel -> tiny MLP -> sigmoid
//           gate -> x_out = x_in * (1 + gate).  grid (CHK, BB), 256 threads.
// ---------------------------------------------------------------------------
__global__ void k_gate(const float* __restrict__ xin, float* xout,
                       const float* __restrict__ W1, const float* __restrict__ b1,
                       const float* __restrict__ W2, const float* __restrict__ b2,
                       int srcm) {
    int b = blockIdx.y, blk = blockIdx.x;
    int tid = threadIdx.x;
    int warp = tid >> 5, lane = tid & 31;

    __shared__ float Msh[HH][DD];              // 16 KB
    __shared__ float Ssh[HH], Bsh[HH];
    __shared__ float W1sh[128], b1sh[16], W2sh[16];
    __shared__ float b2sh;
    __shared__ int allsh;

    {
        const float4* msrc = (const float4*)&g_M[b][0][0];
        float4* mdst = (float4*)&Msh[0][0];
        for (int i = tid; i < HH * DD / 4; i += 256) mdst[i] = msrc[i];
        if (tid < HH) { Ssh[tid] = g_S[b][tid]; Bsh[tid] = g_bias[b][tid]; }
        if (tid >= 32 && tid < 160) W1sh[tid - 32] = W1[tid - 32];
        if (tid >= 160 && tid < 176) b1sh[tid - 160] = b1[tid - 160];
        if (tid >= 176 && tid < 192) W2sh[tid - 176] = W2[tid - 176];
        if (tid == 192) b2sh = b2[0];
        if (tid == 193) allsh = g_all[srcm][b];
    }
    __syncthreads();

    const int TPB = TT / CHK, TPW = TPB / 8;
    int t0 = blk * TPB + warp * TPW;

    for (int i = 0; i < TPW; i++) {
        int t = t0 + i;
        const float4* row = (const float4*)(xin + ((size_t)(b * TT + t)) * DD);
        float4 v[4];
        float s = 0.f, sq = 0.f;
        float dot[8] = {0, 0, 0, 0, 0, 0, 0, 0};
#pragma unroll
        for (int k = 0; k < 4; k++) {
            v[k] = row[k * 32 + lane];
            s  += v[k].x + v[k].y + v[k].z + v[k].w;
            sq += v[k].x * v[k].x + v[k].y * v[k].y + v[k].z * v[k].z + v[k].w * v[k].w;
            int d = k * 128 + lane * 4;
#pragma unroll
            for (int h = 0; h < 8; h++) {
                const float4 mv = *(const float4*)&Msh[h][d];
                dot[h] += v[k].x * mv.x + v[k].y * mv.y + v[k].z * mv.z + v[k].w * mv.w;
            }
        }
#pragma unroll
        for (int off = 16; off; off >>= 1) {
            s  += __shfl_xor_sync(0xffffffffu, s, off);
            sq += __shfl_xor_sync(0xffffffffu, sq, off);
#pragma unroll
            for (int h = 0; h < 8; h++) dot[h] += __shfl_xor_sync(0xffffffffu, dot[h], off);
        }
        float factor = 1.f;
        if (lane == 0) {
            float mean = s * (1.f / DD);
            float var = sq * (1.f / DD) - mean * mean;
            float rstd = rsqrtf(var + EPSF);
            float rel[8];
#pragma unroll
            for (int h = 0; h < 8; h++) rel[h] = rstd * (dot[h] - mean * Ssh[h]) + Bsh[h];
            float gacc = b2sh;
#pragma unroll
            for (int e = 0; e < 16; e++) {
                float a = b1sh[e];
#pragma unroll
                for (int h = 0; h < 8; h++) a += rel[h] * W1sh[e * 8 + h];
                gacc += fmaxf(a, 0.f) * W2sh[e];
            }
            float gate = 1.f / (1.f + expf(-gacc));
            if (allsh) gate = 0.f;
            factor = 1.f + gate;
        }
        factor = __shfl_sync(0xffffffffu, factor, 0);
        float4* orow = (float4*)(xout + ((size_t)(b * TT + t)) * DD);
#pragma unroll
        for (int k = 0; k < 4; k++) {
            float4 o;
            o.x = v[k].x * factor; o.y = v[k].y * factor;
            o.z = v[k].z * factor; o.w = v[k].w * factor;
            orow[k * 32 + lane] = o;
        }
    }
}

// ---------------------------------------------------------------------------
extern "C" void kernel_launch(void* const* d_in, const int* in_sizes, int n_in,
                              void* d_out, int out_size) {
    (void)in_sizes; (void)n_in; (void)out_size;
    const float* x_vid = (const float*)d_in[0];
    const float* x_aud = (const float*)d_in[1];
    const int* vid_kpm = (const int*)d_in[2];
    const int* aud_kpm = (const int*)d_in[3];
    const float* Wq_vid = (const float*)d_in[4];
    const float* Wk_aud = (const float*)d_in[5];
    const float* Wq_aud = (const float*)d_in[6];
    const float* Wk_vid = (const float*)d_in[7];
    const float* vgW1 = (const float*)d_in[8];
    const float* vgb1 = (const float*)d_in[9];
    const float* vgW2 = (const float*)d_in[10];
    const float* vgb2 = (const float*)d_in[11];
    const float* agW1 = (const float*)d_in[12];
    const float* agb1 = (const float*)d_in[13];
    const float* agW2 = (const float*)d_in[14];
    const float* agb2 = (const float*)d_in[15];
    const float* vid_g = (const float*)d_in[16];
    const float* vid_b = (const float*)d_in[17];
    const float* aud_g = (const float*)d_in[18];
    const float* aud_b = (const float*)d_in[19];

    const size_t N = (size_t)BB * TT * DD;
    float* out_vid = (float*)d_out;
    float* out_aud = out_vid + N;

    k_counts<<<8, 256>>>(vid_kpm, aud_kpm);

    const float* cur_vid = x_vid;
    const float* cur_aud = x_aud;
    for (int l = 0; l < LL; l++) {
        size_t wofs = (size_t)l * DD * DD;
        // --- vid stage: source = aud (mask index 1), target = vid ---
        k_reduce<<<dim3(GG, BB), 256>>>(cur_aud, aud_kpm);
        k_mid<<<BB * HH, 512>>>(Wq_vid + wofs, Wk_aud + wofs,
                                vid_g + (size_t)l * DD, vid_b + (size_t)l * DD, 1);
        k_gate<<<dim3(CHK, BB), 256>>>(cur_vid, out_vid,
                                       vgW1 + (size_t)l * 128, vgb1 + (size_t)l * 16,
                                       vgW2 + (size_t)l * 16, vgb2 + l, 1);
        cur_vid = out_vid;
        // --- aud stage: source = updated vid (mask index 0), target = aud ---
        k_reduce<<<dim3(GG, BB), 256>>>(cur_vid, vid_kpm);
        k_mid<<<BB * HH, 512>>>(Wq_aud + wofs, Wk_vid + wofs,
                                aud_g + (size_t)l * DD, aud_b + (size_t)l * DD, 0);
        k_gate<<<dim3(CHK, BB), 256>>>(cur_aud, out_aud,
                                       agW1 + (size_t)l * 128, agb1 + (size_t)l * 16,
                                       agW2 + (size_t)l * 16, agb2 + l, 0);
        cur_aud = out_aud;
    }
}